// round 10
// baseline (speedup 1.0000x reference)
#include <cuda_runtime.h>
#include <cuda_bf16.h>
#include <math.h>
#include <stdint.h>

// x: [B=2, C=64, L=8, H=128, W=128] fp32; P=8 patches; top-2 of 8 experts.
// out = x + sum_top2 w_e * f_e(x_slice); GEMMs via mma.sync.m16n8k16 (bf16).
// pw weights pre-converted (prep kernel) to bf16 fragment-direct layout in
// __device__ globals; GEMM A-fragments are direct coalesced LDG from L2.

typedef unsigned long long u64;

__device__ int   g_topi[2048];
__device__ float g_topw[2048];
__device__ uint4 g_w1[8192];   // pw_in  fragment layout: 8e x 4wo x 4ks x 2sel x 32lane
__device__ uint4 g_w2[4096];   // pw_out fragment layout: 8e x 4wo x 4ks x 32lane

__device__ __forceinline__ u64 pack2(float a, float b) {
    u64 r; asm("mov.b64 %0, {%1, %2};" : "=l"(r) : "f"(a), "f"(b)); return r;
}
__device__ __forceinline__ float2 unpack2(u64 v) {
    float2 r; asm("mov.b64 {%0, %1}, %2;" : "=f"(r.x), "=f"(r.y) : "l"(v)); return r;
}
__device__ __forceinline__ void fma2(u64 &d, u64 a, u64 b) {
    asm("fma.rn.f32x2 %0, %1, %2, %0;" : "+l"(d) : "l"(a), "l"(b));
}
__device__ __forceinline__ void mma_bf16(float d[4], const uint32_t a[4],
                                         uint32_t b0, uint32_t b1) {
    asm volatile(
        "mma.sync.aligned.m16n8k16.row.col.f32.bf16.bf16.f32 "
        "{%0,%1,%2,%3}, {%4,%5,%6,%7}, {%8,%9}, {%0,%1,%2,%3};"
        : "+f"(d[0]), "+f"(d[1]), "+f"(d[2]), "+f"(d[3])
        : "r"(a[0]), "r"(a[1]), "r"(a[2]), "r"(a[3]), "r"(b0), "r"(b1));
}
__device__ __forceinline__ uint32_t bf2pack(float a, float b) {
    __nv_bfloat162 v = __floats2bfloat162_rn(a, b);
    return *reinterpret_cast<uint32_t*>(&v);
}
// Column permutation: logical k-col c -> storage col m, grouping each thread's
// fragment cols {c0, c0+1, c0+8, c0+9} into 4 contiguous elements (1 LDS.64).
__device__ __forceinline__ int permc(int c) {
    return (c & ~15) | (((c >> 1) & 3) << 2) | (((c >> 3) & 1) << 1) | (c & 1);
}
// Activation tile index [p][m], stride 72, with block-XOR so depthwise/epilogue
// stores (p varying by 8) spread banks; warp fragment reads keep p>>3 constant.
__device__ __forceinline__ int aidx(int p, int m) {
    return p * 72 + (m ^ (p & 56));
}

// Shared memory: ht [p][m] bf16 (GEMM1 B), xs [c][p] fp32, dwg union
// { dw fp32 3136 | gated bf16 [p][m] (GEMM2 B) }.
struct SmemLayout {
    __nv_bfloat16 ht[64 * 72];    //  9216 B
    float xs [64 * 68];           // 17408 B
    float dwg[3136];              // 12544 B (gated bf16 needs 9216)
    float lnw[64];
    float lnb[64];
    float bin[128];
    float bout[64];
};
// total ~= 40.5 KB

// ---------------------------------------------------------------------------
// Prep kernel: convert pw weights to bf16 fragment-direct layout (per launch).
// ---------------------------------------------------------------------------
__global__ __launch_bounds__(256) void prep_kernel(
    const float* __restrict__ pw_in_w,
    const float* __restrict__ pw_out_w)
{
    const int id = blockIdx.x * 256 + threadIdx.x;    // 48*256 = 12288
    if (id < 8192) {
        const int lane = id & 31;
        const int rest = id >> 5;       // ((e*4+wo)*4+ks)*2+sel
        const int sel = rest & 1;
        const int ks  = (rest >> 1) & 3;
        const int wo  = (rest >> 3) & 3;
        const int e   = rest >> 5;
        const int r = lane >> 2, tig = lane & 3;
        const float* w = pw_in_w + e * 8192;
        uint32_t v[4];
        #pragma unroll
        for (int j = 0; j < 4; ++j) {
            int o = sel * 64 + wo * 16 + r + (j & 1) * 8;
            int c = ks * 16 + tig * 2 + (j >> 1) * 8;
            v[j] = bf2pack(w[o * 64 + c], w[o * 64 + c + 1]);
        }
        g_w1[id] = make_uint4(v[0], v[1], v[2], v[3]);
    } else {
        const int id2 = id - 8192;
        const int lane = id2 & 31;
        const int rest = id2 >> 5;      // (e*4+wo)*4+ks
        const int ks = rest & 3;
        const int wo = (rest >> 2) & 3;
        const int e  = rest >> 4;
        const int r = lane >> 2, tig = lane & 3;
        const float* w = pw_out_w + e * 4096;
        uint32_t v[4];
        #pragma unroll
        for (int j = 0; j < 4; ++j) {
            int o = wo * 16 + r + (j & 1) * 8;
            int c = ks * 16 + tig * 2 + (j >> 1) * 8;
            v[j] = bf2pack(w[o * 64 + c], w[o * 64 + c + 1]);
        }
        g_w2[id2] = make_uint4(v[0], v[1], v[2], v[3]);
    }
}

// ---------------------------------------------------------------------------
// Router kernel. One block per patch.
// ---------------------------------------------------------------------------
__global__ __launch_bounds__(256) void router_kernel(
    const float* __restrict__ x,
    const float* __restrict__ rw,
    const float* __restrict__ rb)
{
    __shared__ float rmean[64];
    __shared__ float lg[8];
    const int n  = blockIdx.x;
    const int b  = n >> 8;
    const int ph = (n >> 4) & 15;
    const int pw = n & 15;
    const int t  = threadIdx.x;
    const int c  = t >> 2;
    const int part = t & 3;

    const float* xb = x + ((size_t)(b * 64 + c) * 8) * 16384 + (ph * 8) * 128 + pw * 8;
    float s = 0.f;
    #pragma unroll 4
    for (int k = 0; k < 16; ++k) {
        int rowid = part * 16 + k;
        int l = rowid >> 3, r = rowid & 7;
        const float* p = xb + (size_t)l * 16384 + r * 128;
        float4 v0 = *reinterpret_cast<const float4*>(p);
        float4 v1 = *reinterpret_cast<const float4*>(p + 4);
        s += v0.x + v0.y + v0.z + v0.w + v1.x + v1.y + v1.z + v1.w;
    }
    s += __shfl_xor_sync(0xffffffffu, s, 1);
    s += __shfl_xor_sync(0xffffffffu, s, 2);
    if (part == 0) rmean[c] = s * (1.0f / 512.0f);
    __syncthreads();

    if (t < 8) {
        float acc = rb[t];
        #pragma unroll 8
        for (int cc = 0; cc < 64; ++cc) acc += rw[t * 64 + cc] * rmean[cc];
        lg[t] = acc;
    }
    __syncthreads();

    if (t == 0) {
        int i0 = 0; float v0 = lg[0];
        #pragma unroll
        for (int e = 1; e < 8; ++e) if (lg[e] > v0) { v0 = lg[e]; i0 = e; }
        int i1 = -1; float v1 = -1e30f;
        #pragma unroll
        for (int e = 0; e < 8; ++e) if (e != i0 && lg[e] > v1) { v1 = lg[e]; i1 = e; }
        float w0 = 1.0f / (1.0f + expf(v1 - v0));
        g_topi[n * 2]     = i0;
        g_topi[n * 2 + 1] = i1;
        g_topw[n * 2]     = w0;
        g_topw[n * 2 + 1] = 1.0f - w0;
    }
}

// ---------------------------------------------------------------------------
// Main MoE kernel. One CTA per (patch, l) slice. 256 threads.
// ---------------------------------------------------------------------------
__global__ __launch_bounds__(256, 2) void moe_main_kernel(
    const float* __restrict__ x,
    const float* __restrict__ dw_w,
    const float* __restrict__ ln_w,
    const float* __restrict__ ln_b,
    const float* __restrict__ pw_in_b,
    const float* __restrict__ pw_out_b,
    float* __restrict__ out)
{
    extern __shared__ char smem_raw[];
    SmemLayout& S = *reinterpret_cast<SmemLayout*>(smem_raw);

    const int t    = threadIdx.x;
    const int warp = t >> 5;
    const int lane = t & 31;
    const int r    = lane >> 2;   // mma groupID
    const int tig  = lane & 3;    // mma threadID-in-group
    const int wo   = warp & 3;    // o-chunk (16 rows)
    const int wh   = warp >> 2;   // p-half (32 cols)
    const int pb   = wh * 32;

    const int slice = blockIdx.x;
    const int n  = slice >> 3;
    const int l  = slice & 7;
    const int b  = n >> 8;
    const int phh = (n >> 4) & 15;
    const int pww = n & 15;
    const size_t gslice = (size_t)(b * 64) * 8 * 16384 + (size_t)l * 16384
                        + (phh * 8) * 128 + pww * 8;

    // ---- load x slice into xs[c][p] (stride 68) ----
    #pragma unroll
    for (int k = 0; k < 4; ++k) {
        int id = t + k * 256;
        int c = id >> 4, rr = (id >> 1) & 7, hf = id & 1;
        const float* src = x + gslice + (size_t)c * (8 * 16384) + rr * 128 + hf * 4;
        *reinterpret_cast<float4*>(S.xs + c * 68 + rr * 8 + hf * 4) =
            *reinterpret_cast<const float4*>(src);
    }

    const int   e0i = g_topi[n * 2];
    const int   e1i = g_topi[n * 2 + 1];
    const float w0v = g_topw[n * 2];
    const float w1v = g_topw[n * 2 + 1];

    float outacc[4][4];
    #pragma unroll
    for (int nt = 0; nt < 4; ++nt)
        #pragma unroll
        for (int j = 0; j < 4; ++j) outacc[nt][j] = 0.f;

    for (int ei = 0; ei < 2; ++ei) {
        const int   e  = (ei == 0) ? e0i : e1i;
        const float we = (ei == 0) ? w0v : w1v;
        const int e4wo = e * 4 + wo;

        __syncthreads();  // xs ready (iter 0) / prior expert's tile reads done

        // ---- stage depthwise weights + small params ----
        {
            const float* dsrc = dw_w + e * 3136;
            #pragma unroll
            for (int k = 0; k < 4; ++k) {
                int i4 = t + k * 256;
                if (i4 < 784)
                    *reinterpret_cast<float4*>(S.dwg + i4 * 4) =
                        *reinterpret_cast<const float4*>(dsrc + i4 * 4);
            }
            if (t < 64) {
                S.lnw[t]  = ln_w[e * 64 + t];
                S.lnb[t]  = ln_b[e * 64 + t];
                S.bout[t] = pw_out_b[e * 64 + t];
            }
            if (t < 128) S.bin[t] = pw_in_b[e * 128 + t];
        }
        __syncthreads();

        // ---- depthwise 7x7 + LayerNorm -> ht[p][m] bf16 ----
        // thread: c = t/4, rows y0 = 2*(t%4), y0+1; f32x2-packed over the row
        // pair; weight-row reuse: a1's row at yy equals a0's row at yy-1.
        {
            const int c = t >> 2, q = t & 3, y0 = q << 1;
            const int mc = permc(c);
            u64 acc[8];
            #pragma unroll
            for (int i = 0; i < 8; ++i) acc[i] = 0ull;
            const float* xc = S.xs + c * 68;
            const float* wc = S.dwg + c * 49;
            float wold[7];
            bool first = true;
            #pragma unroll
            for (int yy = 0; yy < 8; ++yy) {
                int d0 = yy - y0;
                if (d0 < -3 || d0 > 4) continue;
                float inp[14];
                #pragma unroll
                for (int i = 0; i < 3; ++i) { inp[i] = 0.f; inp[11 + i] = 0.f; }
                float4 va = *reinterpret_cast<const float4*>(xc + yy * 8);
                float4 vb = *reinterpret_cast<const float4*>(xc + yy * 8 + 4);
                inp[3] = va.x; inp[4] = va.y; inp[5]  = va.z; inp[6]  = va.w;
                inp[7] = vb.x; inp[8] = vb.y; inp[9]  = vb.z; inp[10] = vb.w;
                u64 ip[14];
                #pragma unroll
                for (int i = 0; i < 14; ++i) ip[i] = pack2(inp[i], inp[i]);
                if (first) {
                    #pragma unroll
                    for (int j = 0; j < 7; ++j)
                        wold[j] = (d0 + 2 >= 0 && d0 + 2 <= 6) ? wc[(d0 + 2) * 7 + j] : 0.f;
                    first = false;
                }
                float wnew[7];
                #pragma unroll
                for (int j = 0; j < 7; ++j)
                    wnew[j] = (d0 <= 3) ? wc[(d0 + 3) * 7 + j] : 0.f;
                u64 wp[7];
                #pragma unroll
                for (int j = 0; j < 7; ++j) wp[j] = pack2(wnew[j], wold[j]);
                #pragma unroll
                for (int xx = 0; xx < 8; ++xx)
                    #pragma unroll
                    for (int j = 0; j < 7; ++j)
                        fma2(acc[xx], wp[j], ip[xx + j]);
                #pragma unroll
                for (int j = 0; j < 7; ++j) wold[j] = wnew[j];
            }
            float a0[8], a1[8], s = 0.f, s2 = 0.f;
            #pragma unroll
            for (int i = 0; i < 8; ++i) {
                float2 u = unpack2(acc[i]);
                a0[i] = u.x; a1[i] = u.y;
                s  += u.x + u.y;
                s2 += u.x * u.x + u.y * u.y;
            }
            s  += __shfl_xor_sync(0xffffffffu, s, 1);
            s  += __shfl_xor_sync(0xffffffffu, s, 2);
            s2 += __shfl_xor_sync(0xffffffffu, s2, 1);
            s2 += __shfl_xor_sync(0xffffffffu, s2, 2);
            const float mean = s * 0.015625f;
            const float var  = fmaxf(s2 * 0.015625f - mean * mean, 0.f);
            const float rstd = rsqrtf(var + 1e-5f);
            #pragma unroll
            for (int xx = 0; xx < 8; ++xx) {
                int p0 = y0 * 8 + xx;
                float h0 = (a0[xx] - mean) * rstd * S.lnw[p0]     + S.lnb[p0];
                float h1 = (a1[xx] - mean) * rstd * S.lnw[p0 + 8] + S.lnb[p0 + 8];
                S.ht[aidx(p0, mc)]     = __float2bfloat16(h0);
                S.ht[aidx(p0 + 8, mc)] = __float2bfloat16(h1);
            }
        }
        __syncthreads();   // ht ready; dw (in dwg) dead after this point

        // ---- GEMM1 (bf16 mma, A direct-LDG) fused with SiLU gating ----
        // warp (wo, wh): a-rows [16wo,16wo+16), g-rows [64+16wo,...), p [pb,pb+32)
        {
            const int oa = 16 * wo;
            float accA[4][4], accG[4][4];
            #pragma unroll
            for (int nt = 0; nt < 4; ++nt)
                #pragma unroll
                for (int j = 0; j < 4; ++j) { accA[nt][j] = 0.f; accG[nt][j] = 0.f; }
            #pragma unroll
            for (int ks = 0; ks < 4; ++ks) {
                const uint4 va = g_w1[((e4wo * 4 + ks) * 2 + 0) * 32 + lane];
                const uint4 vg = g_w1[((e4wo * 4 + ks) * 2 + 1) * 32 + lane];
                const uint32_t aA[4] = {va.x, va.y, va.z, va.w};
                const uint32_t aG[4] = {vg.x, vg.y, vg.z, vg.w};
                const int m0 = ks * 16 + tig * 4;
                #pragma unroll
                for (int nt = 0; nt < 4; ++nt) {
                    const int p0 = pb + nt * 8;
                    uint2 bv = *reinterpret_cast<const uint2*>(
                        S.ht + (p0 + r) * 72 + (m0 ^ (p0 & 56)));
                    mma_bf16(accA[nt], aA, bv.x, bv.y);
                    mma_bf16(accG[nt], aG, bv.x, bv.y);
                }
            }
            // epilogue: bias + silu gate, store bf16 gated tile
            const float biA0 = S.bin[oa + r],       biA1 = S.bin[oa + r + 8];
            const float biG0 = S.bin[64 + oa + r],  biG1 = S.bin[64 + oa + r + 8];
            const int pc0 = permc(oa + r);     // permc(oa+r+8) = pc0 + 2
            __nv_bfloat16* GT = reinterpret_cast<__nv_bfloat16*>(S.dwg);
            #pragma unroll
            for (int nt = 0; nt < 4; ++nt) {
                const int p0 = pb + nt * 8 + 2 * tig;
                const int xk = (pb + nt * 8) & 56;
                #pragma unroll
                for (int j = 0; j < 4; ++j) {
                    const float a = accA[nt][j] + ((j < 2) ? biA0 : biA1);
                    const float g = accG[nt][j] + ((j < 2) ? biG0 : biG1);
                    const float ga = a / (1.f + __expf(-a)) * g;
                    const int p  = p0 + (j & 1);
                    const int mco = ((j < 2) ? pc0 : pc0 + 2) ^ xk;
                    GT[p * 72 + mco] = __float2bfloat16(ga);
                }
            }
        }
        __syncthreads();

        // ---- GEMM2 (bf16 mma, A direct-LDG): we*(D + bias) into registers ----
        {
            const int o2 = 16 * wo;
            float accO[4][4];
            #pragma unroll
            for (int nt = 0; nt < 4; ++nt)
                #pragma unroll
                for (int j = 0; j < 4; ++j) accO[nt][j] = 0.f;
            const __nv_bfloat16* GT = reinterpret_cast<const __nv_bfloat16*>(S.dwg);
            #pragma unroll
            for (int ks = 0; ks < 4; ++ks) {
                const uint4 vo = g_w2[(e4wo * 4 + ks) * 32 + lane];
                const uint32_t aO[4] = {vo.x, vo.y, vo.z, vo.w};
                const int m0 = ks * 16 + tig * 4;
                #pragma unroll
                for (int nt = 0; nt < 4; ++nt) {
                    const int p0 = pb + nt * 8;
                    uint2 bv = *reinterpret_cast<const uint2*>(
                        GT + (p0 + r) * 72 + (m0 ^ (p0 & 56)));
                    mma_bf16(accO[nt], aO, bv.x, bv.y);
                }
            }
            const float bo0 = S.bout[o2 + r], bo1 = S.bout[o2 + r + 8];
            #pragma unroll
            for (int nt = 0; nt < 4; ++nt)
                #pragma unroll
                for (int j = 0; j < 4; ++j)
                    outacc[nt][j] += we * (accO[nt][j] + ((j < 2) ? bo0 : bo1));
        }
    }

    // ---- final write: out = x + accumulated expert residuals ----
    // thread owns channels {16wo+r, 16wo+r+8}, p = pb + 8nt + 2tig (+1)
    {
        const int o2 = 16 * wo;
        #pragma unroll
        for (int nt = 0; nt < 4; ++nt) {
            const int p0 = pb + nt * 8 + 2 * tig;
            const int rr = p0 >> 3, col = p0 & 7;
            #pragma unroll
            for (int hf = 0; hf < 2; ++hf) {
                const int ch = o2 + r + hf * 8;
                float2 xv = *reinterpret_cast<const float2*>(S.xs + ch * 68 + p0);
                float2 ov;
                ov.x = xv.x + outacc[nt][hf * 2];
                ov.y = xv.y + outacc[nt][hf * 2 + 1];
                float* dst = out + gslice + (size_t)ch * (8 * 16384) + rr * 128 + col;
                *reinterpret_cast<float2*>(dst) = ov;
            }
        }
    }
}

// ---------------------------------------------------------------------------
extern "C" void kernel_launch(void* const* d_in, const int* in_sizes, int n_in,
                              void* d_out, int out_size) {
    const float* x        = (const float*)d_in[0];
    const float* router_w = (const float*)d_in[1];
    const float* router_b = (const float*)d_in[2];
    const float* dw_w     = (const float*)d_in[3];
    // d_in[4] = dw_b: cancels in LayerNorm, unused
    const float* ln_w     = (const float*)d_in[5];
    const float* ln_b     = (const float*)d_in[6];
    const float* pw_in_w  = (const float*)d_in[7];
    const float* pw_in_b  = (const float*)d_in[8];
    const float* pw_out_w = (const float*)d_in[9];
    const float* pw_out_b = (const float*)d_in[10];
    float* out = (float*)d_out;

    const int B = in_sizes[0] / (64 * 8 * 128 * 128);
    const int N = B * 256;
    const int smem_bytes = (int)sizeof(SmemLayout);

    cudaFuncSetAttribute(moe_main_kernel,
                         cudaFuncAttributeMaxDynamicSharedMemorySize, smem_bytes);

    prep_kernel<<<48, 256>>>(pw_in_w, pw_out_w);
    router_kernel<<<N, 256>>>(x, router_w, router_b);
    moe_main_kernel<<<N * 8, 256, smem_bytes>>>(
        x, dw_w, ln_w, ln_b, pw_in_b, pw_out_b, out);
}